// round 1
// baseline (speedup 1.0000x reference)
#include <cuda_runtime.h>

#define NB    256
#define NS    64
#define KACT  8
#define INF_  1024
#define OUTF  1024
#define SUBF  128
#define QF    1024
#define RPC   16     // rows per CTA chunk in the subnet kernel
#define NCHUNK 16    // max chunks per subnet (RPC*NCHUNK = 256 = worst case)

// ---------------- device scratch (static globals: no runtime allocation) ----------
__device__ int   g_cnt[NS];
__device__ int   g_off[NS];
__device__ int   g_sel_s[NB * KACT];
__device__ float g_sel_w[NB * KACT];
__device__ int   g_asg_b[NB * KACT];       // compacted: batch row per assignment
__device__ float g_asg_w[NB * KACT];       // compacted: softmax weight per assignment
__device__ int   g_map[NB * KACT];         // (b,slot) -> compact index
__device__ float g_opart[NB * KACT * OUTF]; // 8 MB partial outputs

// ---------------- kernel 0: zero counters -----------------------------------------
__global__ void colak_zero() {
    if (threadIdx.x < NS) g_cnt[threadIdx.x] = 0;
}

// ---------------- kernel 1: attention + top-8 + softmax + tally -------------------
__global__ void __launch_bounds__(256) colak_attn(const float* __restrict__ q,
                                                  const float* __restrict__ Wk,
                                                  const float* __restrict__ bk) {
    __shared__ float qs[QF];
    __shared__ float att[NS];
    const int b    = blockIdx.x;
    const int tid  = threadIdx.x;
    const int w    = tid >> 5;
    const int lane = tid & 31;

    for (int i = tid; i < QF; i += 256) qs[i] = q[b * QF + i];
    __syncthreads();

    // warp w computes subnets w*8 .. w*8+7, lanes split the 1024-dim
    const float4* q4 = (const float4*)qs;
    for (int k = 0; k < 8; k++) {
        int s = w * 8 + k;
        const float4* wr = (const float4*)(Wk + s * QF);
        float acc = 0.f;
        #pragma unroll
        for (int i = lane; i < QF / 4; i += 32) {
            float4 a = wr[i];
            float4 c = q4[i];
            acc += a.x * c.x + a.y * c.y + a.z * c.z + a.w * c.w;
        }
        #pragma unroll
        for (int o = 16; o; o >>= 1) acc += __shfl_xor_sync(0xffffffffu, acc, o);
        if (lane == 0) att[s] = acc + bk[s];
    }
    __syncthreads();

    if (w == 0) {
        // each lane owns att[lane] and att[lane+32]; exact top-8 by rank
        float v0 = att[lane], v1 = att[lane + 32];
        int r0 = 0, r1 = 0;
        #pragma unroll
        for (int j = 0; j < NS; j++) {
            float a = att[j];
            r0 += (a > v0) || (a == v0 && j < lane);
            r1 += (a > v1) || (a == v1 && j < lane + 32);
        }
        bool k0 = r0 < KACT, k1 = r1 < KACT;

        float m = fmaxf(k0 ? v0 : -1e30f, k1 ? v1 : -1e30f);
        #pragma unroll
        for (int o = 16; o; o >>= 1) m = fmaxf(m, __shfl_xor_sync(0xffffffffu, m, o));

        float e0 = k0 ? expf(v0 - m) : 0.f;
        float e1 = k1 ? expf(v1 - m) : 0.f;
        float sm = e0 + e1;
        #pragma unroll
        for (int o = 16; o; o >>= 1) sm += __shfl_xor_sync(0xffffffffu, sm, o);

        unsigned m0 = __ballot_sync(0xffffffffu, k0);
        unsigned m1 = __ballot_sync(0xffffffffu, k1);
        unsigned lt = (1u << lane) - 1u;
        int base1 = __popc(m0);
        if (k0) {
            int slot = __popc(m0 & lt);
            g_sel_s[b * KACT + slot] = lane;
            g_sel_w[b * KACT + slot] = e0 / sm;
            atomicAdd(&g_cnt[lane], 1);
        }
        if (k1) {
            int slot = base1 + __popc(m1 & lt);
            g_sel_s[b * KACT + slot] = lane + 32;
            g_sel_w[b * KACT + slot] = e1 / sm;
            atomicAdd(&g_cnt[lane + 32], 1);
        }
    }
}

// ---------------- kernel 2: prefix-sum + compact scatter (one block) --------------
__global__ void __launch_bounds__(256) colak_scatter() {
    __shared__ int off_s[NS];
    __shared__ int fill[NS];
    const int tid = threadIdx.x;
    if (tid == 0) {
        int run = 0;
        for (int s = 0; s < NS; s++) { off_s[s] = run; run += g_cnt[s]; }
    }
    __syncthreads();
    if (tid < NS) { g_off[tid] = off_s[tid]; fill[tid] = off_s[tid]; }
    __syncthreads();
    for (int idx = tid; idx < NB * KACT; idx += 256) {
        int s = g_sel_s[idx];
        int p = atomicAdd(&fill[s], 1);
        g_asg_b[p] = idx >> 3;
        g_asg_w[p] = g_sel_w[idx];
        g_map[idx] = p;
    }
}

// ---------------- kernel 3: grouped dual low-rank GEMM ----------------------------
// smem layout (dynamic):
//   Xs : 16 rows x 1024 f32 (as float4)  = 16384 floats
//   Vs : 128 x 132 f32 tile (pitch 132)  = 16896 floats
//   Ts : 16 x 128 f32                    =  2048 floats
#define VS_PITCH 132
#define SMEM_B_FLOATS (16384 + 128 * VS_PITCH + 2048)

__global__ void __launch_bounds__(256) colak_subnet(const float* __restrict__ x,
                                                    const float* __restrict__ V0,
                                                    const float* __restrict__ V1) {
    const int c = blockIdx.x;   // chunk
    const int s = blockIdx.y;   // subnet
    const int n = g_cnt[s];
    const int r0 = c * RPC;
    if (r0 >= n) return;
    const int m = min(RPC, n - r0);
    const int gbase = g_off[s] + r0;

    extern __shared__ float smem[];
    float4* Xs4 = (float4*)smem;                 // [16][256] float4
    float*  Vs  = smem + 16384;                  // [128][132]
    float*  Ts  = smem + 16384 + 128 * VS_PITCH; // [16][128]
    __shared__ int   rows[RPC];
    __shared__ float wts[RPC];

    const int tid  = threadIdx.x;
    const int w    = tid >> 5;
    const int lane = tid & 31;
    const int j    = ((w & 3) << 5) + lane;  // 0..127 (output col of current stage)
    const int rb   = (w >> 2) << 3;          // 0 or 8 (row half)

    if (tid < RPC) {
        rows[tid] = (tid < m) ? g_asg_b[gbase + tid] : -1;
        wts[tid]  = (tid < m) ? g_asg_w[gbase + tid] : 0.f;
    }
    __syncthreads();

    // load X rows (zero-fill padding rows)
    #pragma unroll 4
    for (int f = tid; f < RPC * (INF_ / 4); f += 256) {
        int r = f >> 8;          // /256 float4 per row
        int col = f & 255;
        float4 v = make_float4(0.f, 0.f, 0.f, 0.f);
        if (r < m) v = ((const float4*)(x + (size_t)rows[r] * INF_))[col];
        Xs4[f] = v;
    }

    // ---------------- stage 1: T[r][j] = wt[r] * sum_i X[r][i] * V0[j][i] ---------
    float acc[8];
    #pragma unroll
    for (int r = 0; r < 8; r++) acc[r] = 0.f;

    const float* v0base = V0 + (size_t)s * SUBF * INF_;
    for (int it = 0; it < INF_ / 128; it++) {
        __syncthreads();
        #pragma unroll
        for (int f = tid; f < 4096; f += 256) {
            int row = f >> 5;
            int col = (f & 31) << 2;
            *(float4*)(&Vs[row * VS_PITCH + col]) =
                *(const float4*)(v0base + (size_t)row * INF_ + it * 128 + col);
        }
        __syncthreads();
        const float*  vr = &Vs[j * VS_PITCH];
        const float4* xr = Xs4 + it * 32;
        #pragma unroll 8
        for (int i4 = 0; i4 < 32; i4++) {
            float4 v = *(const float4*)(vr + (i4 << 2));
            #pragma unroll
            for (int r = 0; r < 8; r++) {
                float4 xx = xr[(rb + r) * 256 + i4];  // broadcast across warp
                acc[r] += v.x * xx.x + v.y * xx.y + v.z * xx.z + v.w * xx.w;
            }
        }
    }
    #pragma unroll
    for (int r = 0; r < 8; r++) Ts[(rb + r) * SUBF + j] = acc[r] * wts[rb + r];
    __syncthreads();

    // ---------------- stage 2: O[r][o] = sum_j T[r][j] * V1[o][j] -----------------
    const float* v1base = V1 + (size_t)s * OUTF * SUBF;
    const int ol = j;  // output col within the o-tile
    for (int ot = 0; ot < OUTF / 128; ot++) {
        __syncthreads();
        #pragma unroll
        for (int f = tid; f < 4096; f += 256) {
            int row = f >> 5;
            int col = (f & 31) << 2;
            *(float4*)(&Vs[row * VS_PITCH + col]) =
                *(const float4*)(v1base + (size_t)(ot * 128 + row) * SUBF + col);
        }
        __syncthreads();
        float a2[8];
        #pragma unroll
        for (int r = 0; r < 8; r++) a2[r] = 0.f;
        const float* vr = &Vs[ol * VS_PITCH];
        #pragma unroll 8
        for (int j4 = 0; j4 < 32; j4++) {
            float4 v = *(const float4*)(vr + (j4 << 2));
            #pragma unroll
            for (int r = 0; r < 8; r++) {
                float4 t = *(const float4*)(&Ts[(rb + r) * SUBF + (j4 << 2)]); // broadcast
                a2[r] += v.x * t.x + v.y * t.y + v.z * t.z + v.w * t.w;
            }
        }
        #pragma unroll
        for (int r = 0; r < 8; r++) {
            if (rb + r < m)
                g_opart[(size_t)(gbase + rb + r) * OUTF + ot * 128 + ol] = a2[r];
        }
    }
}

// ---------------- kernel 4: reduce 8 partials per batch row -----------------------
__global__ void __launch_bounds__(256) colak_reduce(float* __restrict__ out) {
    __shared__ int mp[KACT];
    const int b = blockIdx.x;
    const int tid = threadIdx.x;
    if (tid < KACT) mp[tid] = g_map[b * KACT + tid];
    __syncthreads();
    // 1024 floats = 256 float4 per row; 256 threads -> one float4 each
    const float4* op = (const float4*)g_opart;
    float4 sum = make_float4(0.f, 0.f, 0.f, 0.f);
    #pragma unroll
    for (int k = 0; k < KACT; k++) {
        float4 v = op[(size_t)mp[k] * (OUTF / 4) + tid];
        sum.x += v.x; sum.y += v.y; sum.z += v.z; sum.w += v.w;
    }
    ((float4*)out)[(size_t)b * (OUTF / 4) + tid] = sum;
}

// ---------------- host launcher ----------------------------------------------------
extern "C" void kernel_launch(void* const* d_in, const int* in_sizes, int n_in,
                              void* d_out, int out_size) {
    const float* x  = (const float*)d_in[0];
    const float* q  = (const float*)d_in[1];
    const float* Wk = (const float*)d_in[2];
    const float* bk = (const float*)d_in[3];
    const float* V0 = (const float*)d_in[4];
    const float* V1 = (const float*)d_in[5];
    float* out = (float*)d_out;

    const int smem_b = SMEM_B_FLOATS * 4;
    cudaFuncSetAttribute(colak_subnet, cudaFuncAttributeMaxDynamicSharedMemorySize, smem_b);

    colak_zero<<<1, 64>>>();
    colak_attn<<<NB, 256>>>(q, Wk, bk);
    colak_scatter<<<1, 256>>>();
    colak_subnet<<<dim3(NCHUNK, NS), 256, smem_b>>>(x, V0, V1);
    colak_reduce<<<NB, 256>>>(out);
}

// round 2
// speedup vs baseline: 1.1520x; 1.1520x over previous
#include <cuda_runtime.h>

#define NB    256
#define NS    64
#define KACT  8
#define INF_  1024
#define OUTF  1024
#define SUBF  128
#define QF    1024

// ---------------- device scratch (static globals: no runtime allocation) ----------
__device__ int   g_cnt[NS];
__device__ int   g_off[NS];
__device__ int   g_sel_s[NB * KACT];
__device__ float g_sel_w[NB * KACT];
__device__ int   g_asg_b[NB * KACT];          // compacted: batch row per assignment
__device__ float g_asg_w[NB * KACT];          // compacted: softmax weight per assignment
__device__ int   g_map[NB * KACT];            // (b,slot) -> compact index
__device__ float g_T[(NB * KACT + 8) * SUBF]; // stage-1 output (weight pre-applied), +8 row pad
__device__ float g_opart[NB * KACT * OUTF];   // 8 MB partial outputs

// ---------------- cp.async helpers ------------------------------------------------
__device__ __forceinline__ void cp16(void* s, const void* g) {
    unsigned sa = (unsigned)__cvta_generic_to_shared(s);
    asm volatile("cp.async.cg.shared.global [%0], [%1], 16;\n" :: "r"(sa), "l"(g));
}
#define CP_COMMIT()  asm volatile("cp.async.commit_group;\n")
#define CP_WAIT(n)   asm volatile("cp.async.wait_group %0;\n" :: "n"(n))

// ---------------- kernel 0: zero counters -----------------------------------------
__global__ void colak_zero() {
    if (threadIdx.x < NS) g_cnt[threadIdx.x] = 0;
}

// ---------------- kernel 1: attention + top-8 + softmax + tally -------------------
__global__ void __launch_bounds__(256) colak_attn(const float* __restrict__ q,
                                                  const float* __restrict__ Wk,
                                                  const float* __restrict__ bk) {
    __shared__ float qs[QF];
    __shared__ float att[NS];
    const int b    = blockIdx.x;
    const int tid  = threadIdx.x;
    const int w    = tid >> 5;
    const int lane = tid & 31;

    for (int i = tid; i < QF; i += 256) qs[i] = q[b * QF + i];
    __syncthreads();

    const float4* q4 = (const float4*)qs;
    for (int k = 0; k < 8; k++) {
        int s = w * 8 + k;
        const float4* wr = (const float4*)(Wk + s * QF);
        float acc = 0.f;
        #pragma unroll
        for (int i = lane; i < QF / 4; i += 32) {
            float4 a = wr[i];
            float4 c = q4[i];
            acc += a.x * c.x + a.y * c.y + a.z * c.z + a.w * c.w;
        }
        #pragma unroll
        for (int o = 16; o; o >>= 1) acc += __shfl_xor_sync(0xffffffffu, acc, o);
        if (lane == 0) att[s] = acc + bk[s];
    }
    __syncthreads();

    if (w == 0) {
        float v0 = att[lane], v1 = att[lane + 32];
        int r0 = 0, r1 = 0;
        #pragma unroll
        for (int j = 0; j < NS; j++) {
            float a = att[j];
            r0 += (a > v0) || (a == v0 && j < lane);
            r1 += (a > v1) || (a == v1 && j < lane + 32);
        }
        bool k0 = r0 < KACT, k1 = r1 < KACT;

        float m = fmaxf(k0 ? v0 : -1e30f, k1 ? v1 : -1e30f);
        #pragma unroll
        for (int o = 16; o; o >>= 1) m = fmaxf(m, __shfl_xor_sync(0xffffffffu, m, o));

        float e0 = k0 ? expf(v0 - m) : 0.f;
        float e1 = k1 ? expf(v1 - m) : 0.f;
        float sm = e0 + e1;
        #pragma unroll
        for (int o = 16; o; o >>= 1) sm += __shfl_xor_sync(0xffffffffu, sm, o);

        unsigned m0 = __ballot_sync(0xffffffffu, k0);
        unsigned m1 = __ballot_sync(0xffffffffu, k1);
        unsigned lt = (1u << lane) - 1u;
        int base1 = __popc(m0);
        if (k0) {
            int slot = __popc(m0 & lt);
            g_sel_s[b * KACT + slot] = lane;
            g_sel_w[b * KACT + slot] = e0 / sm;
            atomicAdd(&g_cnt[lane], 1);
        }
        if (k1) {
            int slot = base1 + __popc(m1 & lt);
            g_sel_s[b * KACT + slot] = lane + 32;
            g_sel_w[b * KACT + slot] = e1 / sm;
            atomicAdd(&g_cnt[lane + 32], 1);
        }
    }
}

// ---------------- kernel 2: prefix-sum + compact scatter (one block) --------------
__global__ void __launch_bounds__(256) colak_scatter() {
    __shared__ int off_s[NS];
    __shared__ int fill[NS];
    const int tid = threadIdx.x;
    if (tid == 0) {
        int run = 0;
        for (int s = 0; s < NS; s++) { off_s[s] = run; run += g_cnt[s]; }
    }
    __syncthreads();
    if (tid < NS) { g_off[tid] = off_s[tid]; fill[tid] = off_s[tid]; }
    __syncthreads();
    for (int idx = tid; idx < NB * KACT; idx += 256) {
        int s = g_sel_s[idx];
        int p = atomicAdd(&fill[s], 1);
        g_asg_b[p] = idx >> 3;
        g_asg_w[p] = g_sel_w[idx];
        g_map[idx] = p;
    }
}

// ---------------- kernel T: stage 1  T[r][j] = wt[r] * sum_i X[r][i]*V0[s][j][i] ---
// grid = (32 chunks, 64 subnets), 128 threads. 8 rows per CTA.
// smem: Xs 8x1024 f32 (32KB) + double-buffered V0 tile 128j x 64i, pitch 68 (2x34.8KB)
#define TP 68
#define SMEM_T_BYTES ((8 * 1024 + 2 * 128 * TP) * 4)

__global__ void __launch_bounds__(128) colak_T(const float* __restrict__ x,
                                               const float* __restrict__ V0) {
    const int s = blockIdx.y;
    const int c = blockIdx.x;
    const int n = g_cnt[s];
    if (c * 8 >= n) return;
    const int m = min(8, n - c * 8);
    const int gbase = g_off[s] + c * 8;

    extern __shared__ float smem[];
    float* Xs = smem;             // [8][1024]
    float* Vb = smem + 8 * 1024;  // 2 x [128][TP]
    __shared__ int   rows[8];
    __shared__ float wts[8];

    const int tid  = threadIdx.x;
    const int w    = tid >> 5;
    const int lane = tid & 31;
    const int j    = w * 32 + lane;   // 0..127

    if (tid < 8) {
        rows[tid] = (tid < m) ? g_asg_b[gbase + tid] : 0;
        wts[tid]  = (tid < m) ? g_asg_w[gbase + tid] : 0.f;
    }
    __syncthreads();

    const float* v0 = V0 + (size_t)s * SUBF * INF_;

    // prefetch V0 tile 0 (128 rows x 64 floats)
    {
        float* dst = Vb;
        #pragma unroll
        for (int k = 0; k < 16; k++) {
            int idx = k * 128 + tid;        // 0..2047
            int jr = idx >> 4, seg = idx & 15;
            cp16(dst + jr * TP + seg * 4, v0 + (size_t)jr * INF_ + seg * 4);
        }
        CP_COMMIT();
    }

    // load X rows (zero-fill padding rows); overlaps with cp.async above
    for (int f = tid; f < 8 * 256; f += 128) {
        int r = f >> 8, col = f & 255;
        float4 v = make_float4(0.f, 0.f, 0.f, 0.f);
        if (r < m) v = ((const float4*)(x + (size_t)rows[r] * INF_))[col];
        ((float4*)Xs)[f] = v;
    }

    float acc[8];
    #pragma unroll
    for (int r = 0; r < 8; r++) acc[r] = 0.f;

    for (int it = 0; it < 16; it++) {
        const int buf = it & 1;
        if (it + 1 < 16) {
            float* dst = Vb + (buf ^ 1) * 128 * TP;
            const float* src = v0 + (it + 1) * 64;
            #pragma unroll
            for (int k = 0; k < 16; k++) {
                int idx = k * 128 + tid;
                int jr = idx >> 4, seg = idx & 15;
                cp16(dst + jr * TP + seg * 4, src + (size_t)jr * INF_ + seg * 4);
            }
            CP_COMMIT();
            CP_WAIT(1);
        } else {
            CP_WAIT(0);
        }
        __syncthreads();

        const float*  vr = Vb + buf * 128 * TP + j * TP;
        const float4* xr = (const float4*)Xs + it * 16;
        #pragma unroll
        for (int i4 = 0; i4 < 16; i4++) {
            float4 v = *(const float4*)(vr + (i4 << 2));
            #pragma unroll
            for (int r = 0; r < 8; r++) {
                float4 xx = xr[r * 256 + i4];   // broadcast across warp
                acc[r] += v.x * xx.x + v.y * xx.y + v.z * xx.z + v.w * xx.w;
            }
        }
        __syncthreads();   // protect buf before it is overwritten
    }

    #pragma unroll
    for (int r = 0; r < 8; r++)
        if (r < m) g_T[(size_t)(gbase + r) * SUBF + j] = acc[r] * wts[r];
}

// ---------------- kernel O: stage 2  O[r][o] = sum_j T[r][j]*V1[s][o][j] ----------
// grid = (8 o-tiles, 64 subnets), 128 threads. V1 tile resident in smem.
// smem: V1 tile 128o x 128j pitch 132 (67.6KB) + T chunk 8x128 (4KB)
#define OP 132
#define SMEM_O_BYTES ((128 * OP + 8 * SUBF) * 4)

__global__ void __launch_bounds__(128) colak_O(const float* __restrict__ V1) {
    const int s  = blockIdx.y;
    const int ot = blockIdx.x;
    const int n  = g_cnt[s];
    if (n == 0) return;
    const int gbase = g_off[s];

    extern __shared__ float smem[];
    float* Vs = smem;            // [128][OP]
    float* Ts = smem + 128 * OP; // [8][128]

    const int tid  = threadIdx.x;
    const int w    = tid >> 5;
    const int lane = tid & 31;
    const int o    = w * 32 + lane;   // 0..127

    const float* v1 = V1 + (size_t)s * OUTF * SUBF + (size_t)ot * 128 * SUBF;
    #pragma unroll
    for (int k = 0; k < 32; k++) {
        int idx = k * 128 + tid;          // 0..4095 float4 chunks
        int orow = idx >> 5, seg = idx & 31;
        cp16(Vs + orow * OP + seg * 4, v1 + (size_t)orow * SUBF + seg * 4);
    }
    CP_COMMIT();
    CP_WAIT(0);
    __syncthreads();

    for (int c0 = 0; c0 < n; c0 += 8) {
        const int m = min(8, n - c0);
        __syncthreads();   // protect Ts from previous iteration's readers
        for (int f = tid; f < 8 * 32; f += 128) {   // 8 rows x 32 float4
            int r = f >> 5, seg = f & 31;
            ((float4*)Ts)[f] = *(const float4*)(g_T + (size_t)(gbase + c0 + r) * SUBF + seg * 4);
        }
        __syncthreads();

        float acc[8];
        #pragma unroll
        for (int r = 0; r < 8; r++) acc[r] = 0.f;

        const float* vr = Vs + o * OP;
        #pragma unroll
        for (int j4 = 0; j4 < 32; j4++) {
            float4 v = *(const float4*)(vr + (j4 << 2));
            #pragma unroll
            for (int r = 0; r < 8; r++) {
                float4 t = *(const float4*)(Ts + r * SUBF + (j4 << 2));  // broadcast
                acc[r] += v.x * t.x + v.y * t.y + v.z * t.z + v.w * t.w;
            }
        }

        #pragma unroll
        for (int r = 0; r < 8; r++)
            if (r < m)
                g_opart[(size_t)(gbase + c0 + r) * OUTF + ot * 128 + o] = acc[r];
    }
}

// ---------------- kernel 4: reduce 8 partials per batch row -----------------------
__global__ void __launch_bounds__(256) colak_reduce(float* __restrict__ out) {
    __shared__ int mp[KACT];
    const int b = blockIdx.x;
    const int tid = threadIdx.x;
    if (tid < KACT) mp[tid] = g_map[b * KACT + tid];
    __syncthreads();
    const float4* op = (const float4*)g_opart;
    float4 sum = make_float4(0.f, 0.f, 0.f, 0.f);
    #pragma unroll
    for (int k = 0; k < KACT; k++) {
        float4 v = op[(size_t)mp[k] * (OUTF / 4) + tid];
        sum.x += v.x; sum.y += v.y; sum.z += v.z; sum.w += v.w;
    }
    ((float4*)out)[(size_t)b * (OUTF / 4) + tid] = sum;
}

// ---------------- host launcher ----------------------------------------------------
extern "C" void kernel_launch(void* const* d_in, const int* in_sizes, int n_in,
                              void* d_out, int out_size) {
    const float* x  = (const float*)d_in[0];
    const float* q  = (const float*)d_in[1];
    const float* Wk = (const float*)d_in[2];
    const float* bk = (const float*)d_in[3];
    const float* V0 = (const float*)d_in[4];
    const float* V1 = (const float*)d_in[5];
    float* out = (float*)d_out;

    cudaFuncSetAttribute(colak_T, cudaFuncAttributeMaxDynamicSharedMemorySize, SMEM_T_BYTES);
    cudaFuncSetAttribute(colak_O, cudaFuncAttributeMaxDynamicSharedMemorySize, SMEM_O_BYTES);

    colak_zero<<<1, 64>>>();
    colak_attn<<<NB, 256>>>(q, Wk, bk);
    colak_scatter<<<1, 256>>>();
    colak_T<<<dim3(32, NS), 128, SMEM_T_BYTES>>>(x, V0);
    colak_O<<<dim3(8, NS), 128, SMEM_O_BYTES>>>(V1);
    colak_reduce<<<NB, 256>>>(out);
}